// round 17
// baseline (speedup 1.0000x reference)
#include <cuda_runtime.h>
#include <cstdint>

// ----------------------------------------------------------------------------
// BaseLUTLayer = multilinear polynomial eval in Moebius coefficient basis.
//   prep_kernel: transpose x -> xT[IN][B] (64x64 float4 tiles).
//   lut_fold_kernel: in-warp Moebius (shfl-xor butterflies), then nested-
//     Horner f32x2 fold (BPT=4). REGISTER-LEAN body: coefficient pairs are
//     consumed two-at-a-time with eager bit0+1 folding (peak v-temps 16 regs
//     instead of 32) and progressive bit-4 accumulation, so the kernel fits
//     5 blocks/SM (__launch_bounds__(256,5), <=51 regs).
// ----------------------------------------------------------------------------

#define O_TILE 8
#define BPT    4
#define B_TILE (32 * BPT)   // 128

__device__ float g_xT[4 * 1024 * 1024];   // transposed x scratch

static __device__ __forceinline__ unsigned long long pack2(float lo, float hi) {
    unsigned long long r;
    asm("mov.b64 %0, {%1, %2};" : "=l"(r) : "f"(lo), "f"(hi));
    return r;
}
static __device__ __forceinline__ void unpack2(unsigned long long v, float& lo, float& hi) {
    asm("mov.b64 {%0, %1}, %2;" : "=f"(lo), "=f"(hi) : "l"(v));
}
static __device__ __forceinline__ unsigned long long fma2(unsigned long long a,
                                                          unsigned long long b,
                                                          unsigned long long c) {
    unsigned long long d;
    asm("fma.rn.f32x2 %0, %1, %2, %3;" : "=l"(d) : "l"(a), "l"(b), "l"(c));
    return d;
}

// ---- prep: transpose only ---------------------------------------------------
__global__ __launch_bounds__(256)
void prep_kernel(const float* __restrict__ x, float* __restrict__ xT,
                 int B, int IN, int tiles_x) {
    __shared__ float tile[64][65];
    const int tid = threadIdx.x;
    const int c0 = (blockIdx.x % tiles_x) * 64;    // IN base
    const int r0 = (blockIdx.x / tiles_x) * 64;    // B base
    float4 v[4];
#pragma unroll
    for (int p = 0; p < 4; p++) {
        int idx  = p * 256 + tid;
        int row  = idx >> 4;
        int col4 = idx & 15;
        int r = r0 + row, c = c0 + col4 * 4;
        v[p] = (r < B && c + 3 < IN)
             ? *reinterpret_cast<const float4*>(&x[(size_t)r * IN + c])
             : make_float4(0.f, 0.f, 0.f, 0.f);
    }
#pragma unroll
    for (int p = 0; p < 4; p++) {
        int idx  = p * 256 + tid;
        int row  = idx >> 4;
        int col4 = idx & 15;
        tile[row][col4 * 4 + 0] = v[p].x;
        tile[row][col4 * 4 + 1] = v[p].y;
        tile[row][col4 * 4 + 2] = v[p].z;
        tile[row][col4 * 4 + 3] = v[p].w;
    }
    __syncthreads();
#pragma unroll
    for (int p = 0; p < 4; p++) {
        int idx = p * 256 + tid;
        int inl = idx >> 4;
        int b4  = idx & 15;
        int in = c0 + inl, bb = r0 + b4 * 4;
        if (in < IN && bb + 3 < B) {
            float4 w = make_float4(tile[b4 * 4 + 0][inl],
                                   tile[b4 * 4 + 1][inl],
                                   tile[b4 * 4 + 2][inl],
                                   tile[b4 * 4 + 3][inl]);
            *reinterpret_cast<float4*>(&xT[(size_t)in * B + bb]) = w;
        }
    }
}

// ---- fold: in-warp Moebius + lean f32x2 nested Horner, BPT=4, 5 blk/SM -----
__global__ __launch_bounds__(32 * O_TILE, 5)
void lut_fold_kernel(const float* __restrict__ xT,
                     const float* __restrict__ lut_table,
                     const int*   __restrict__ mapping,
                     float* __restrict__ out,
                     int B, int OUT) {
    __shared__ ulonglong2 s_lut[O_TILE][32];
    __shared__ float      s_res[O_TILE][B_TILE + 4];

    const int lane = threadIdx.x;
    const int ty   = threadIdx.y;
    const int tid  = ty * 32 + lane;
    const int b0   = blockIdx.x * B_TILE;
    const int o0   = blockIdx.y * O_TILE;
    int o = o0 + ty;
    if (o >= OUT) o = OUT - 1;

    // ---- in-warp Moebius: lane owns lut entries (2*lane, 2*lane+1) ---------
    float2 eu = __ldg(reinterpret_cast<const float2*>(&lut_table[(size_t)o * 64 + 2 * lane]));
    float e0 = eu.x, e1 = eu.y;
    e1 -= e0;                                           // bit 0 (intra-lane)
#pragma unroll
    for (int j = 0; j < 5; j++) {                       // bits 1..5 butterflies
        int s = 1 << j;
        float p0 = __shfl_xor_sync(0xffffffffu, e0, s);
        float p1 = __shfl_xor_sync(0xffffffffu, e1, s);
        if (lane & s) { e0 -= p0; e1 -= p1; }
    }

    // per-warp mapping row (uniform across lanes)
    int m[6];
#pragma unroll
    for (int j = 0; j < 6; j++) m[j] = __ldg(&mapping[(size_t)o * 6 + j]);

    // x loads: one LDG.128 per bit = both f32x2 sets
    const int bq = b0 + lane * BPT;
    const bool vb = (bq + BPT - 1 < B);
    unsigned long long Xa[6], Xb[6];
#pragma unroll
    for (int j = 0; j < 6; j++) {
        if (vb) {
            ulonglong2 xv = *reinterpret_cast<const ulonglong2*>(&xT[(size_t)m[j] * B + bq]);
            Xa[j] = xv.x;
            Xb[j] = xv.y;
        } else {
            Xa[j] = 0ull; Xb[j] = 0ull;
        }
    }

    // duplicated coefficient pairs -> smem (per-warp row, warp-sync only)
    {
        ulonglong2 e;
        e.x = pack2(e0, e0);
        e.y = pack2(e1, e1);
        s_lut[ty][lane] = e;
    }
    __syncwarp();

    const ulonglong2* lrow = &s_lut[ty][0];

    // ---- register-lean fold: eager bit0+1, progressive bit4 accumulation ---
    unsigned long long acca, acc2a, accb, acc2b;
#pragma unroll
    for (int g = 0; g < 4; g++) {
        unsigned long long wa[4], wb[4];
#pragma unroll
        for (int i = 0; i < 4; i++) {
            ulonglong2 ep = lrow[g * 8 + 2 * i];        // pair 2i   (LDS.128)
            ulonglong2 eq = lrow[g * 8 + 2 * i + 1];    // pair 2i+1 (LDS.128)
            unsigned long long ta = fma2(Xa[0], ep.y, ep.x);   // bit 0
            unsigned long long tb = fma2(Xa[0], eq.y, eq.x);
            wa[i] = fma2(Xa[1], tb, ta);                       // bit 1
            unsigned long long ua = fma2(Xb[0], ep.y, ep.x);
            unsigned long long ub = fma2(Xb[0], eq.y, eq.x);
            wb[i] = fma2(Xb[1], ub, ua);
        }
        unsigned long long ya0 = fma2(Xa[2], wa[1], wa[0]);    // bit 2
        unsigned long long ya1 = fma2(Xa[2], wa[3], wa[2]);
        unsigned long long rga = fma2(Xa[3], ya1, ya0);        // bit 3
        unsigned long long yb0 = fma2(Xb[2], wb[1], wb[0]);
        unsigned long long yb1 = fma2(Xb[2], wb[3], wb[2]);
        unsigned long long rgb = fma2(Xb[3], yb1, yb0);

        if (g == 0)      { acca  = rga; accb  = rgb; }
        else if (g == 1) { acca  = fma2(Xa[4], rga, acca);     // bit 4
                           accb  = fma2(Xb[4], rgb, accb); }
        else if (g == 2) { acc2a = rga; acc2b = rgb; }
        else             { acc2a = fma2(Xa[4], rga, acc2a);
                           acc2b = fma2(Xb[4], rgb, acc2b); }
    }
    unsigned long long resa = fma2(Xa[5], acc2a, acca);        // bit 5
    unsigned long long resb = fma2(Xb[5], acc2b, accb);

    float r0f, r1f, r2f, r3f;
    unpack2(resa, r0f, r1f);
    unpack2(resb, r2f, r3f);
    *reinterpret_cast<float4*>(&s_res[ty][lane * BPT]) = make_float4(r0f, r1f, r2f, r3f);
    __syncthreads();

    // writeout: o fastest, float4 stores (full 32B sectors)
    int bw   = tid >> 1;          // 0..127
    int half = tid & 1;
    int oo   = o0 + half * 4;
    int bg   = b0 + bw;
    if (bg < B && oo + 3 < OUT) {
        float4 val = make_float4(s_res[half * 4 + 0][bw],
                                 s_res[half * 4 + 1][bw],
                                 s_res[half * 4 + 2][bw],
                                 s_res[half * 4 + 3][bw]);
        *reinterpret_cast<float4*>(&out[(size_t)bg * OUT + oo]) = val;
    }
}

extern "C" void kernel_launch(void* const* d_in, const int* in_sizes, int n_in,
                              void* d_out, int out_size) {
    const float* x       = (const float*)d_in[0];
    const float* lut     = (const float*)d_in[1];
    const int*   mapping = (const int*)d_in[2];
    float*       out     = (float*)d_out;

    int OUT = in_sizes[2] / 6;          // mapping is (OUT, 6)
    int B   = out_size / OUT;           // out is (B, OUT)
    int IN  = in_sizes[0] / B;          // x is (B, IN)

    float* xT = nullptr;
    cudaGetSymbolAddress((void**)&xT, g_xT);

    int tiles_x = (IN + 63) / 64;
    int tiles_y = (B + 63) / 64;
    prep_kernel<<<tiles_x * tiles_y, 256>>>(x, xT, B, IN, tiles_x);

    dim3 blk(32, O_TILE);
    dim3 grd((B + B_TILE - 1) / B_TILE, (OUT + O_TILE - 1) / O_TILE);
    lut_fold_kernel<<<grd, blk>>>(xT, lut, mapping, out, B, OUT);
}